// round 1
// baseline (speedup 1.0000x reference)
#include <cuda_runtime.h>
#include <math.h>

#define NN 100000
#define EE 1600000
#define NBLK_SCAN ((NN + 1023) / 1024)

// ---------------- device scratch (no allocations allowed) ----------------
__device__ int g_deg[NN];
__device__ int g_rowptr[NN + 1];
__device__ int g_fill[NN];
__device__ int g_csr[EE];
__device__ int g_blksum[NBLK_SCAN];

__device__ float g_agg[(size_t)NN * 128];
__device__ float g_h1[(size_t)NN * 128];
__device__ float g_h2[(size_t)NN * 128];
__device__ float g_t3[(size_t)NN * 64];
__device__ float g_agg3[(size_t)NN * 64];
__device__ float g_o3[(size_t)NN * 64];

// ---------------- CSR construction ----------------
__global__ void k_zero_deg() {
    int i = blockIdx.x * blockDim.x + threadIdx.x;
    if (i < NN) g_deg[i] = 0;
}

__global__ void k_hist(const int* __restrict__ dst, int E) {
    int e = blockIdx.x * blockDim.x + threadIdx.x;
    if (e < E) atomicAdd(&g_deg[dst[e]], 1);
}

__global__ void k_scan1() {
    __shared__ int s[1024];
    int i = threadIdx.x;
    int gid = blockIdx.x * 1024 + i;
    int v = (gid < NN) ? g_deg[gid] : 0;
    s[i] = v;
    __syncthreads();
    for (int off = 1; off < 1024; off <<= 1) {
        int add = (i >= off) ? s[i - off] : 0;
        __syncthreads();
        s[i] += add;
        __syncthreads();
    }
    if (gid < NN) g_rowptr[gid] = s[i] - v;
    if (i == 1023) g_blksum[blockIdx.x] = s[1023];
}

__global__ void k_scan2() {
    if (threadIdx.x == 0 && blockIdx.x == 0) {
        int acc = 0;
        for (int b = 0; b < NBLK_SCAN; b++) {
            int t = g_blksum[b];
            g_blksum[b] = acc;
            acc += t;
        }
    }
}

__global__ void k_scan3(int E) {
    int gid = blockIdx.x * blockDim.x + threadIdx.x;
    if (gid < NN) {
        int rp = g_rowptr[gid] + g_blksum[gid >> 10];
        g_rowptr[gid] = rp;
        g_fill[gid] = rp;
    } else if (gid == NN) {
        g_rowptr[NN] = E;
    }
}

__global__ void k_scatter(const int* __restrict__ src, const int* __restrict__ dst, int E) {
    int e = blockIdx.x * blockDim.x + threadIdx.x;
    if (e < E) {
        int p = atomicAdd(&g_fill[dst[e]], 1);
        g_csr[p] = src[e];
    }
}

// ---------------- mean aggregation (warp per node) ----------------
__global__ void k_aggr128(const float* __restrict__ xin, float* __restrict__ out) {
    int wid = blockIdx.x * (blockDim.x >> 5) + (threadIdx.x >> 5);
    int lane = threadIdx.x & 31;
    if (wid >= NN) return;
    int beg = g_rowptr[wid], end = g_rowptr[wid + 1];
    float4 acc = make_float4(0.f, 0.f, 0.f, 0.f);
    int j = beg;
    for (; j + 1 < end; j += 2) {
        int s0 = g_csr[j], s1 = g_csr[j + 1];
        float4 v0 = *(const float4*)(xin + (size_t)s0 * 128 + lane * 4);
        float4 v1 = *(const float4*)(xin + (size_t)s1 * 128 + lane * 4);
        acc.x += v0.x + v1.x; acc.y += v0.y + v1.y;
        acc.z += v0.z + v1.z; acc.w += v0.w + v1.w;
    }
    if (j < end) {
        int s0 = g_csr[j];
        float4 v0 = *(const float4*)(xin + (size_t)s0 * 128 + lane * 4);
        acc.x += v0.x; acc.y += v0.y; acc.z += v0.z; acc.w += v0.w;
    }
    float inv = 1.f / fmaxf((float)(end - beg), 1.f);
    acc.x *= inv; acc.y *= inv; acc.z *= inv; acc.w *= inv;
    *(float4*)(out + (size_t)wid * 128 + lane * 4) = acc;
}

__global__ void k_aggr64(const float* __restrict__ xin, float* __restrict__ out) {
    int wid = blockIdx.x * (blockDim.x >> 5) + (threadIdx.x >> 5);
    int lane = threadIdx.x & 31;
    if (wid >= NN) return;
    int beg = g_rowptr[wid], end = g_rowptr[wid + 1];
    float2 acc = make_float2(0.f, 0.f);
    int j = beg;
    for (; j + 1 < end; j += 2) {
        int s0 = g_csr[j], s1 = g_csr[j + 1];
        float2 v0 = *(const float2*)(xin + (size_t)s0 * 64 + lane * 2);
        float2 v1 = *(const float2*)(xin + (size_t)s1 * 64 + lane * 2);
        acc.x += v0.x + v1.x; acc.y += v0.y + v1.y;
    }
    if (j < end) {
        int s0 = g_csr[j];
        float2 v0 = *(const float2*)(xin + (size_t)s0 * 64 + lane * 2);
        acc.x += v0.x; acc.y += v0.y;
    }
    float inv = 1.f / fmaxf((float)(end - beg), 1.f);
    acc.x *= inv; acc.y *= inv;
    *(float2*)(out + (size_t)wid * 64 + lane * 2) = acc;
}

// ---------------- fused dual GEMM + BN + ReLU (layers 1,2) ----------------
// out = relu( bn( A1@W1^T + A2@W2^T + bias ) )   [NN,128] x [128,128]
__global__ __launch_bounds__(256) void k_gemm_dual_bnrelu(
    const float* __restrict__ A1, const float* __restrict__ W1,
    const float* __restrict__ A2, const float* __restrict__ W2,
    const float* __restrict__ bias, const float* __restrict__ gamma,
    const float* __restrict__ beta, const float* __restrict__ rmean,
    const float* __restrict__ rvar, float* __restrict__ out)
{
    __shared__ float As[16][132];
    __shared__ float Ws[16][132];
    const int t = threadIdx.x;
    const int tx = t & 15, ty = t >> 4;
    const int row0 = blockIdx.x * 128;

    float acc[8][8];
#pragma unroll
    for (int i = 0; i < 8; i++)
#pragma unroll
        for (int j = 0; j < 8; j++) acc[i][j] = 0.f;

#pragma unroll
    for (int pass = 0; pass < 2; pass++) {
        const float* A = pass ? A2 : A1;
        const float* W = pass ? W2 : W1;
        for (int k0 = 0; k0 < 128; k0 += 16) {
#pragma unroll
            for (int it = 0; it < 2; it++) {
                int idx = t + it * 256;
                int m = idx >> 2, f4 = idx & 3;
                int gr = row0 + m;
                float4 v = make_float4(0.f, 0.f, 0.f, 0.f);
                if (gr < NN) v = *(const float4*)(A + (size_t)gr * 128 + k0 + f4 * 4);
                As[f4 * 4 + 0][m] = v.x; As[f4 * 4 + 1][m] = v.y;
                As[f4 * 4 + 2][m] = v.z; As[f4 * 4 + 3][m] = v.w;
                float4 w = *(const float4*)(W + (size_t)m * 128 + k0 + f4 * 4);
                Ws[f4 * 4 + 0][m] = w.x; Ws[f4 * 4 + 1][m] = w.y;
                Ws[f4 * 4 + 2][m] = w.z; Ws[f4 * 4 + 3][m] = w.w;
            }
            __syncthreads();
#pragma unroll
            for (int kk = 0; kk < 16; kk++) {
                float4 a0 = *(const float4*)&As[kk][ty * 8];
                float4 a1 = *(const float4*)&As[kk][ty * 8 + 4];
                float4 w0 = *(const float4*)&Ws[kk][tx * 8];
                float4 w1 = *(const float4*)&Ws[kk][tx * 8 + 4];
                float a[8] = {a0.x, a0.y, a0.z, a0.w, a1.x, a1.y, a1.z, a1.w};
                float w[8] = {w0.x, w0.y, w0.z, w0.w, w1.x, w1.y, w1.z, w1.w};
#pragma unroll
                for (int i = 0; i < 8; i++)
#pragma unroll
                    for (int j = 0; j < 8; j++)
                        acc[i][j] = fmaf(a[i], w[j], acc[i][j]);
            }
            __syncthreads();
        }
    }

    float sc[8], sh[8];
#pragma unroll
    for (int j = 0; j < 8; j++) {
        int o = tx * 8 + j;
        float s = gamma[o] * rsqrtf(rvar[o] + 1e-5f);
        sc[j] = s;
        sh[j] = beta[o] + (bias[o] - rmean[o]) * s;
    }
#pragma unroll
    for (int i = 0; i < 8; i++) {
        int gr = row0 + ty * 8 + i;
        if (gr >= NN) continue;
        float4 o0, o1;
        o0.x = fmaxf(acc[i][0] * sc[0] + sh[0], 0.f);
        o0.y = fmaxf(acc[i][1] * sc[1] + sh[1], 0.f);
        o0.z = fmaxf(acc[i][2] * sc[2] + sh[2], 0.f);
        o0.w = fmaxf(acc[i][3] * sc[3] + sh[3], 0.f);
        o1.x = fmaxf(acc[i][4] * sc[4] + sh[4], 0.f);
        o1.y = fmaxf(acc[i][5] * sc[5] + sh[5], 0.f);
        o1.z = fmaxf(acc[i][6] * sc[6] + sh[6], 0.f);
        o1.w = fmaxf(acc[i][7] * sc[7] + sh[7], 0.f);
        *(float4*)(out + (size_t)gr * 128 + tx * 8) = o0;
        *(float4*)(out + (size_t)gr * 128 + tx * 8 + 4) = o1;
    }
}

// ---------------- GEMM to 64 outputs (layer 3) ----------------
// out = A@W^T (+ addv) (+ bias)     [NN,128] x [64,128] -> [NN,64]
__global__ __launch_bounds__(256) void k_gemm64(
    const float* __restrict__ A, const float* __restrict__ W,
    const float* __restrict__ addv, const float* __restrict__ bias,
    float* __restrict__ out)
{
    __shared__ float As[16][132];
    __shared__ float Ws[16][68];
    const int t = threadIdx.x;
    const int tx = t & 15, ty = t >> 4;
    const int row0 = blockIdx.x * 128;

    float acc[8][4];
#pragma unroll
    for (int i = 0; i < 8; i++)
#pragma unroll
        for (int j = 0; j < 4; j++) acc[i][j] = 0.f;

    for (int k0 = 0; k0 < 128; k0 += 16) {
#pragma unroll
        for (int it = 0; it < 2; it++) {
            int idx = t + it * 256;
            int m = idx >> 2, f4 = idx & 3;
            int gr = row0 + m;
            float4 v = make_float4(0.f, 0.f, 0.f, 0.f);
            if (gr < NN) v = *(const float4*)(A + (size_t)gr * 128 + k0 + f4 * 4);
            As[f4 * 4 + 0][m] = v.x; As[f4 * 4 + 1][m] = v.y;
            As[f4 * 4 + 2][m] = v.z; As[f4 * 4 + 3][m] = v.w;
        }
        {
            int o = t >> 2, f4 = t & 3;
            float4 w = *(const float4*)(W + (size_t)o * 128 + k0 + f4 * 4);
            Ws[f4 * 4 + 0][o] = w.x; Ws[f4 * 4 + 1][o] = w.y;
            Ws[f4 * 4 + 2][o] = w.z; Ws[f4 * 4 + 3][o] = w.w;
        }
        __syncthreads();
#pragma unroll
        for (int kk = 0; kk < 16; kk++) {
            float4 a0 = *(const float4*)&As[kk][ty * 8];
            float4 a1 = *(const float4*)&As[kk][ty * 8 + 4];
            float4 w0 = *(const float4*)&Ws[kk][tx * 4];
            float a[8] = {a0.x, a0.y, a0.z, a0.w, a1.x, a1.y, a1.z, a1.w};
            float w[4] = {w0.x, w0.y, w0.z, w0.w};
#pragma unroll
            for (int i = 0; i < 8; i++)
#pragma unroll
                for (int j = 0; j < 4; j++)
                    acc[i][j] = fmaf(a[i], w[j], acc[i][j]);
        }
        __syncthreads();
    }

    float bb[4] = {0.f, 0.f, 0.f, 0.f};
    if (bias) {
        bb[0] = bias[tx * 4 + 0]; bb[1] = bias[tx * 4 + 1];
        bb[2] = bias[tx * 4 + 2]; bb[3] = bias[tx * 4 + 3];
    }
#pragma unroll
    for (int i = 0; i < 8; i++) {
        int gr = row0 + ty * 8 + i;
        if (gr >= NN) continue;
        float4 r;
        r.x = acc[i][0] + bb[0];
        r.y = acc[i][1] + bb[1];
        r.z = acc[i][2] + bb[2];
        r.w = acc[i][3] + bb[3];
        if (addv) {
            float4 av = *(const float4*)(addv + (size_t)gr * 64 + tx * 4);
            r.x += av.x; r.y += av.y; r.z += av.z; r.w += av.w;
        }
        *(float4*)(out + (size_t)gr * 64 + tx * 4) = r;
    }
}

// ---------------- log_softmax over 64 (warp per row) ----------------
__global__ void k_lsm(const float* __restrict__ in, float* __restrict__ out) {
    int wid = blockIdx.x * (blockDim.x >> 5) + (threadIdx.x >> 5);
    int lane = threadIdx.x & 31;
    if (wid >= NN) return;
    float v0 = in[(size_t)wid * 64 + lane];
    float v1 = in[(size_t)wid * 64 + 32 + lane];
    float m = fmaxf(v0, v1);
#pragma unroll
    for (int o = 16; o > 0; o >>= 1) m = fmaxf(m, __shfl_xor_sync(0xffffffffu, m, o));
    float s = expf(v0 - m) + expf(v1 - m);
#pragma unroll
    for (int o = 16; o > 0; o >>= 1) s += __shfl_xor_sync(0xffffffffu, s, o);
    float l = m + logf(s);
    out[(size_t)wid * 64 + lane] = v0 - l;
    out[(size_t)wid * 64 + 32 + lane] = v1 - l;
}

// ---------------- launch ----------------
extern "C" void kernel_launch(void* const* d_in, const int* in_sizes, int n_in,
                              void* d_out, int out_size) {
    const float* x   = (const float*)d_in[0];
    const int*   src = (const int*)d_in[1];
    const int*   dst = (const int*)d_in[2];
    const float* W1l = (const float*)d_in[3];
    const float* W1r = (const float*)d_in[4];
    const float* b1  = (const float*)d_in[5];
    const float* g1  = (const float*)d_in[6];
    const float* be1 = (const float*)d_in[7];
    const float* rm1 = (const float*)d_in[8];
    const float* rv1 = (const float*)d_in[9];
    const float* W2l = (const float*)d_in[10];
    const float* W2r = (const float*)d_in[11];
    const float* b2  = (const float*)d_in[12];
    const float* g2  = (const float*)d_in[13];
    const float* be2 = (const float*)d_in[14];
    const float* rm2 = (const float*)d_in[15];
    const float* rv2 = (const float*)d_in[16];
    const float* W3l = (const float*)d_in[17];
    const float* W3r = (const float*)d_in[18];
    const float* b3  = (const float*)d_in[19];
    float* out = (float*)d_out;
    int E = in_sizes[1];

    float *p_agg, *p_h1, *p_h2, *p_t3, *p_agg3, *p_o3;
    cudaGetSymbolAddress((void**)&p_agg,  g_agg);
    cudaGetSymbolAddress((void**)&p_h1,   g_h1);
    cudaGetSymbolAddress((void**)&p_h2,   g_h2);
    cudaGetSymbolAddress((void**)&p_t3,   g_t3);
    cudaGetSymbolAddress((void**)&p_agg3, g_agg3);
    cudaGetSymbolAddress((void**)&p_o3,   g_o3);

    // CSR build (src/dst shared across all 3 layers)
    k_zero_deg<<<(NN + 255) / 256, 256>>>();
    k_hist<<<(E + 255) / 256, 256>>>(dst, E);
    k_scan1<<<NBLK_SCAN, 1024>>>();
    k_scan2<<<1, 32>>>();
    k_scan3<<<(NN + 1 + 255) / 256, 256>>>(E);
    k_scatter<<<(E + 255) / 256, 256>>>(src, dst, E);

    const int gemm_blocks = (NN + 127) / 128;

    // layer 1
    k_aggr128<<<NN / 8, 256>>>(x, p_agg);
    k_gemm_dual_bnrelu<<<gemm_blocks, 256>>>(p_agg, W1l, x, W1r,
                                             b1, g1, be1, rm1, rv1, p_h1);
    // layer 2
    k_aggr128<<<NN / 8, 256>>>(p_h1, p_agg);
    k_gemm_dual_bnrelu<<<gemm_blocks, 256>>>(p_agg, W2l, p_h1, W2r,
                                             b2, g2, be2, rm2, rv2, p_h2);
    // layer 3: transform-then-aggregate (agg is linear) to halve gather width
    k_gemm64<<<gemm_blocks, 256>>>(p_h2, W3l, nullptr, nullptr, p_t3);
    k_aggr64<<<NN / 8, 256>>>(p_t3, p_agg3);
    k_gemm64<<<gemm_blocks, 256>>>(p_h2, W3r, p_agg3, b3, p_o3);
    k_lsm<<<NN / 8, 256>>>(p_o3, out);
}

// round 2
// speedup vs baseline: 1.1649x; 1.1649x over previous
#include <cuda_runtime.h>
#include <math.h>
#include <stdint.h>

#define NN 100000
#define EE 1600000
#define NBLK_SCAN ((NN + 1023) / 1024)

// ---------------- device scratch (no allocations allowed) ----------------
__device__ int g_deg[NN];
__device__ int g_rowptr[NN + 1];
__device__ int g_fill[NN];
__device__ int g_csr[EE];
__device__ int g_blksum[NBLK_SCAN];

__device__ float g_agg[(size_t)NN * 128];
__device__ float g_h1[(size_t)NN * 128];
__device__ float g_h2[(size_t)NN * 128];
__device__ float g_t3[(size_t)NN * 64];
__device__ float g_agg3[(size_t)NN * 64];
__device__ float g_o3[(size_t)NN * 64];

// ---------------- CSR construction ----------------
__global__ void k_zero_deg() {
    int i = blockIdx.x * blockDim.x + threadIdx.x;
    if (i < NN) g_deg[i] = 0;
}

__global__ void k_hist(const int* __restrict__ dst, int E) {
    int e = blockIdx.x * blockDim.x + threadIdx.x;
    if (e < E) atomicAdd(&g_deg[dst[e]], 1);
}

__global__ void k_scan1() {
    __shared__ int s[1024];
    int i = threadIdx.x;
    int gid = blockIdx.x * 1024 + i;
    int v = (gid < NN) ? g_deg[gid] : 0;
    s[i] = v;
    __syncthreads();
    for (int off = 1; off < 1024; off <<= 1) {
        int add = (i >= off) ? s[i - off] : 0;
        __syncthreads();
        s[i] += add;
        __syncthreads();
    }
    if (gid < NN) g_rowptr[gid] = s[i] - v;
    if (i == 1023) g_blksum[blockIdx.x] = s[1023];
}

__global__ void k_scan2() {
    if (threadIdx.x == 0 && blockIdx.x == 0) {
        int acc = 0;
        for (int b = 0; b < NBLK_SCAN; b++) {
            int t = g_blksum[b];
            g_blksum[b] = acc;
            acc += t;
        }
    }
}

__global__ void k_scan3(int E) {
    int gid = blockIdx.x * blockDim.x + threadIdx.x;
    if (gid < NN) {
        int rp = g_rowptr[gid] + g_blksum[gid >> 10];
        g_rowptr[gid] = rp;
        g_fill[gid] = rp;
    } else if (gid == NN) {
        g_rowptr[NN] = E;
    }
}

__global__ void k_scatter(const int* __restrict__ src, const int* __restrict__ dst, int E) {
    int e = blockIdx.x * blockDim.x + threadIdx.x;
    if (e < E) {
        int p = atomicAdd(&g_fill[dst[e]], 1);
        g_csr[p] = src[e];
    }
}

// ---------------- mean aggregation (warp per node) ----------------
__global__ void k_aggr128(const float* __restrict__ xin, float* __restrict__ out) {
    int wid = blockIdx.x * (blockDim.x >> 5) + (threadIdx.x >> 5);
    int lane = threadIdx.x & 31;
    if (wid >= NN) return;
    int beg = g_rowptr[wid], end = g_rowptr[wid + 1];
    float4 acc = make_float4(0.f, 0.f, 0.f, 0.f);
    int j = beg;
    for (; j + 1 < end; j += 2) {
        int s0 = g_csr[j], s1 = g_csr[j + 1];
        float4 v0 = *(const float4*)(xin + (size_t)s0 * 128 + lane * 4);
        float4 v1 = *(const float4*)(xin + (size_t)s1 * 128 + lane * 4);
        acc.x += v0.x + v1.x; acc.y += v0.y + v1.y;
        acc.z += v0.z + v1.z; acc.w += v0.w + v1.w;
    }
    if (j < end) {
        int s0 = g_csr[j];
        float4 v0 = *(const float4*)(xin + (size_t)s0 * 128 + lane * 4);
        acc.x += v0.x; acc.y += v0.y; acc.z += v0.z; acc.w += v0.w;
    }
    float inv = 1.f / fmaxf((float)(end - beg), 1.f);
    acc.x *= inv; acc.y *= inv; acc.z *= inv; acc.w *= inv;
    *(float4*)(out + (size_t)wid * 128 + lane * 4) = acc;
}

__global__ void k_aggr64(const float* __restrict__ xin, float* __restrict__ out) {
    int wid = blockIdx.x * (blockDim.x >> 5) + (threadIdx.x >> 5);
    int lane = threadIdx.x & 31;
    if (wid >= NN) return;
    int beg = g_rowptr[wid], end = g_rowptr[wid + 1];
    float2 acc = make_float2(0.f, 0.f);
    int j = beg;
    for (; j + 1 < end; j += 2) {
        int s0 = g_csr[j], s1 = g_csr[j + 1];
        float2 v0 = *(const float2*)(xin + (size_t)s0 * 64 + lane * 2);
        float2 v1 = *(const float2*)(xin + (size_t)s1 * 64 + lane * 2);
        acc.x += v0.x + v1.x; acc.y += v0.y + v1.y;
    }
    if (j < end) {
        int s0 = g_csr[j];
        float2 v0 = *(const float2*)(xin + (size_t)s0 * 64 + lane * 2);
        acc.x += v0.x; acc.y += v0.y;
    }
    float inv = 1.f / fmaxf((float)(end - beg), 1.f);
    acc.x *= inv; acc.y *= inv;
    *(float2*)(out + (size_t)wid * 64 + lane * 2) = acc;
}

// ---------------- tf32 helpers ----------------
__device__ __forceinline__ void tf32split(float v, unsigned& hi, unsigned& lo) {
    unsigned h;
    asm("cvt.rna.tf32.f32 %0, %1;" : "=r"(h) : "f"(v));
    float l = v - __uint_as_float(h);
    unsigned lt;
    asm("cvt.rna.tf32.f32 %0, %1;" : "=r"(lt) : "f"(l));
    hi = h; lo = lt;
}

#define MMA_TF32(C, A, b0, b1)                                                \
    asm volatile(                                                             \
        "mma.sync.aligned.m16n8k8.row.col.f32.tf32.tf32.f32 "                 \
        "{%0,%1,%2,%3},{%4,%5,%6,%7},{%8,%9},{%0,%1,%2,%3};"                  \
        : "+f"((C)[0]), "+f"((C)[1]), "+f"((C)[2]), "+f"((C)[3])              \
        : "r"((A)[0]), "r"((A)[1]), "r"((A)[2]), "r"((A)[3]),                 \
          "r"(b0), "r"(b1))

// ---------------- fused dual GEMM + BN + ReLU via tf32 MMA (layers 1,2) ----------------
// out = relu( bn( A1@W1^T + A2@W2^T + bias ) )   [NN,128] x [128,128]
// 3xTF32 split for fp32-like accuracy.
__global__ __launch_bounds__(256, 2) void k_gemm_dual_bnrelu(
    const float* __restrict__ A1, const float* __restrict__ W1,
    const float* __restrict__ A2, const float* __restrict__ W2,
    const float* __restrict__ bias, const float* __restrict__ gamma,
    const float* __restrict__ beta, const float* __restrict__ rmean,
    const float* __restrict__ rvar, float* __restrict__ out)
{
    // stride 20 floats: bank = (20*(lane/4)+lane%4)%32 hits all 32 banks
    __shared__ float sAhi[128][20], sAlo[128][20];
    __shared__ float sWhi[128][20], sWlo[128][20];
    __shared__ float s_sc[128], s_sh[128];

    const int t = threadIdx.x;
    const int lane = t & 31, wid = t >> 5;
    const int wr = wid & 3;       // warp row 0..3 (32 rows each)
    const int wc = wid >> 2;      // warp col 0..1 (64 cols each)
    const int g = lane >> 2, tg = lane & 3;
    const int row0 = blockIdx.x * 128;

    if (t < 128) {
        float s = gamma[t] * rsqrtf(rvar[t] + 1e-5f);
        s_sc[t] = s;
        s_sh[t] = beta[t] + (bias[t] - rmean[t]) * s;
    }

    float c[2][8][4];
#pragma unroll
    for (int mt = 0; mt < 2; mt++)
#pragma unroll
        for (int nt = 0; nt < 8; nt++)
#pragma unroll
            for (int q = 0; q < 4; q++) c[mt][nt][q] = 0.f;

#pragma unroll
    for (int pass = 0; pass < 2; pass++) {
        const float* A = pass ? A2 : A1;
        const float* W = pass ? W2 : W1;
        for (int k0 = 0; k0 < 128; k0 += 16) {
            __syncthreads();
            // load A chunk: 128x16 = 512 float4, 2 per thread
#pragma unroll
            for (int i = 0; i < 2; i++) {
                int f = t + i * 256;
                int r = f >> 2, c4 = f & 3;
                int gr = row0 + r;
                float4 v = make_float4(0.f, 0.f, 0.f, 0.f);
                if (gr < NN) v = *(const float4*)(A + (size_t)gr * 128 + k0 + c4 * 4);
                unsigned h0, l0, h1, l1, h2, l2, h3, l3;
                tf32split(v.x, h0, l0); tf32split(v.y, h1, l1);
                tf32split(v.z, h2, l2); tf32split(v.w, h3, l3);
                float* ph = &sAhi[r][c4 * 4];
                float* pl = &sAlo[r][c4 * 4];
                *(float4*)ph = make_float4(__uint_as_float(h0), __uint_as_float(h1),
                                           __uint_as_float(h2), __uint_as_float(h3));
                *(float4*)pl = make_float4(__uint_as_float(l0), __uint_as_float(l1),
                                           __uint_as_float(l2), __uint_as_float(l3));
            }
            // load W chunk: 128x16 = 512 float4, 2 per thread
#pragma unroll
            for (int i = 0; i < 2; i++) {
                int f = t + i * 256;
                int r = f >> 2, c4 = f & 3;
                float4 v = *(const float4*)(W + (size_t)r * 128 + k0 + c4 * 4);
                unsigned h0, l0, h1, l1, h2, l2, h3, l3;
                tf32split(v.x, h0, l0); tf32split(v.y, h1, l1);
                tf32split(v.z, h2, l2); tf32split(v.w, h3, l3);
                float* ph = &sWhi[r][c4 * 4];
                float* pl = &sWlo[r][c4 * 4];
                *(float4*)ph = make_float4(__uint_as_float(h0), __uint_as_float(h1),
                                           __uint_as_float(h2), __uint_as_float(h3));
                *(float4*)pl = make_float4(__uint_as_float(l0), __uint_as_float(l1),
                                           __uint_as_float(l2), __uint_as_float(l3));
            }
            __syncthreads();

#pragma unroll
            for (int ks = 0; ks < 2; ks++) {
                const int kk = ks * 8;
                unsigned ahi[2][4], alo[2][4];
#pragma unroll
                for (int mt = 0; mt < 2; mt++) {
                    int r = wr * 32 + mt * 16 + g;
                    ahi[mt][0] = __float_as_uint(sAhi[r][kk + tg]);
                    ahi[mt][1] = __float_as_uint(sAhi[r + 8][kk + tg]);
                    ahi[mt][2] = __float_as_uint(sAhi[r][kk + tg + 4]);
                    ahi[mt][3] = __float_as_uint(sAhi[r + 8][kk + tg + 4]);
                    alo[mt][0] = __float_as_uint(sAlo[r][kk + tg]);
                    alo[mt][1] = __float_as_uint(sAlo[r + 8][kk + tg]);
                    alo[mt][2] = __float_as_uint(sAlo[r][kk + tg + 4]);
                    alo[mt][3] = __float_as_uint(sAlo[r + 8][kk + tg + 4]);
                }
#pragma unroll
                for (int nt = 0; nt < 8; nt++) {
                    int n = wc * 64 + nt * 8 + g;
                    unsigned bh0 = __float_as_uint(sWhi[n][kk + tg]);
                    unsigned bh1 = __float_as_uint(sWhi[n][kk + tg + 4]);
                    unsigned bl0 = __float_as_uint(sWlo[n][kk + tg]);
                    unsigned bl1 = __float_as_uint(sWlo[n][kk + tg + 4]);
#pragma unroll
                    for (int mt = 0; mt < 2; mt++) {
                        MMA_TF32(c[mt][nt], ahi[mt], bh0, bh1);
                        MMA_TF32(c[mt][nt], ahi[mt], bl0, bl1);
                        MMA_TF32(c[mt][nt], alo[mt], bh0, bh1);
                    }
                }
            }
        }
    }

    // epilogue: BN + ReLU, float2 stores
#pragma unroll
    for (int mt = 0; mt < 2; mt++) {
#pragma unroll
        for (int i = 0; i < 2; i++) {
            int r = row0 + wr * 32 + mt * 16 + g + i * 8;
            if (r >= NN) continue;
#pragma unroll
            for (int nt = 0; nt < 8; nt++) {
                int col = wc * 64 + nt * 8 + 2 * tg;
                float v0 = c[mt][nt][2 * i];
                float v1 = c[mt][nt][2 * i + 1];
                v0 = fmaxf(v0 * s_sc[col] + s_sh[col], 0.f);
                v1 = fmaxf(v1 * s_sc[col + 1] + s_sh[col + 1], 0.f);
                *(float2*)(out + (size_t)r * 128 + col) = make_float2(v0, v1);
            }
        }
    }
}

// ---------------- GEMM to 64 outputs via tf32 MMA (layer 3) ----------------
// out = A@W^T (+ addv) (+ bias)     [NN,128] x [64,128] -> [NN,64]
__global__ __launch_bounds__(256, 2) void k_gemm64(
    const float* __restrict__ A, const float* __restrict__ W,
    const float* __restrict__ addv, const float* __restrict__ bias,
    float* __restrict__ out)
{
    __shared__ float sAhi[128][20], sAlo[128][20];
    __shared__ float sWhi[64][20], sWlo[64][20];

    const int t = threadIdx.x;
    const int lane = t & 31, wid = t >> 5;
    const int wr = wid & 3;       // warp row 0..3 (32 rows each)
    const int wc = wid >> 2;      // warp col 0..1 (32 cols each)
    const int g = lane >> 2, tg = lane & 3;
    const int row0 = blockIdx.x * 128;

    float c[2][4][4];
#pragma unroll
    for (int mt = 0; mt < 2; mt++)
#pragma unroll
        for (int nt = 0; nt < 4; nt++)
#pragma unroll
            for (int q = 0; q < 4; q++) c[mt][nt][q] = 0.f;

    for (int k0 = 0; k0 < 128; k0 += 16) {
        __syncthreads();
#pragma unroll
        for (int i = 0; i < 2; i++) {
            int f = t + i * 256;
            int r = f >> 2, c4 = f & 3;
            int gr = row0 + r;
            float4 v = make_float4(0.f, 0.f, 0.f, 0.f);
            if (gr < NN) v = *(const float4*)(A + (size_t)gr * 128 + k0 + c4 * 4);
            unsigned h0, l0, h1, l1, h2, l2, h3, l3;
            tf32split(v.x, h0, l0); tf32split(v.y, h1, l1);
            tf32split(v.z, h2, l2); tf32split(v.w, h3, l3);
            *(float4*)&sAhi[r][c4 * 4] = make_float4(__uint_as_float(h0), __uint_as_float(h1),
                                                     __uint_as_float(h2), __uint_as_float(h3));
            *(float4*)&sAlo[r][c4 * 4] = make_float4(__uint_as_float(l0), __uint_as_float(l1),
                                                     __uint_as_float(l2), __uint_as_float(l3));
        }
        {
            int r = t >> 2, c4 = t & 3;   // 64x16 = 256 float4, 1 per thread
            float4 v = *(const float4*)(W + (size_t)r * 128 + k0 + c4 * 4);
            unsigned h0, l0, h1, l1, h2, l2, h3, l3;
            tf32split(v.x, h0, l0); tf32split(v.y, h1, l1);
            tf32split(v.z, h2, l2); tf32split(v.w, h3, l3);
            *(float4*)&sWhi[r][c4 * 4] = make_float4(__uint_as_float(h0), __uint_as_float(h1),
                                                     __uint_as_float(h2), __uint_as_float(h3));
            *(float4*)&sWlo[r][c4 * 4] = make_float4(__uint_as_float(l0), __uint_as_float(l1),
                                                     __uint_as_float(l2), __uint_as_float(l3));
        }
        __syncthreads();

#pragma unroll
        for (int ks = 0; ks < 2; ks++) {
            const int kk = ks * 8;
            unsigned ahi[2][4], alo[2][4];
#pragma unroll
            for (int mt = 0; mt < 2; mt++) {
                int r = wr * 32 + mt * 16 + g;
                ahi[mt][0] = __float_as_uint(sAhi[r][kk + tg]);
                ahi[mt][1] = __float_as_uint(sAhi[r + 8][kk + tg]);
                ahi[mt][2] = __float_as_uint(sAhi[r][kk + tg + 4]);
                ahi[mt][3] = __float_as_uint(sAhi[r + 8][kk + tg + 4]);
                alo[mt][0] = __float_as_uint(sAlo[r][kk + tg]);
                alo[mt][1] = __float_as_uint(sAlo[r + 8][kk + tg]);
                alo[mt][2] = __float_as_uint(sAlo[r][kk + tg + 4]);
                alo[mt][3] = __float_as_uint(sAlo[r + 8][kk + tg + 4]);
            }
#pragma unroll
            for (int nt = 0; nt < 4; nt++) {
                int n = wc * 32 + nt * 8 + g;
                unsigned bh0 = __float_as_uint(sWhi[n][kk + tg]);
                unsigned bh1 = __float_as_uint(sWhi[n][kk + tg + 4]);
                unsigned bl0 = __float_as_uint(sWlo[n][kk + tg]);
                unsigned bl1 = __float_as_uint(sWlo[n][kk + tg + 4]);
#pragma unroll
                for (int mt = 0; mt < 2; mt++) {
                    MMA_TF32(c[mt][nt], ahi[mt], bh0, bh1);
                    MMA_TF32(c[mt][nt], ahi[mt], bl0, bl1);
                    MMA_TF32(c[mt][nt], alo[mt], bh0, bh1);
                }
            }
        }
    }

#pragma unroll
    for (int mt = 0; mt < 2; mt++) {
#pragma unroll
        for (int i = 0; i < 2; i++) {
            int r = row0 + wr * 32 + mt * 16 + g + i * 8;
            if (r >= NN) continue;
#pragma unroll
            for (int nt = 0; nt < 4; nt++) {
                int col = wc * 32 + nt * 8 + 2 * tg;
                float v0 = c[mt][nt][2 * i];
                float v1 = c[mt][nt][2 * i + 1];
                if (bias) { v0 += bias[col]; v1 += bias[col + 1]; }
                if (addv) {
                    float2 av = *(const float2*)(addv + (size_t)r * 64 + col);
                    v0 += av.x; v1 += av.y;
                }
                *(float2*)(out + (size_t)r * 64 + col) = make_float2(v0, v1);
            }
        }
    }
}

// ---------------- log_softmax over 64 (warp per row) ----------------
__global__ void k_lsm(const float* __restrict__ in, float* __restrict__ out) {
    int wid = blockIdx.x * (blockDim.x >> 5) + (threadIdx.x >> 5);
    int lane = threadIdx.x & 31;
    if (wid >= NN) return;
    float v0 = in[(size_t)wid * 64 + lane];
    float v1 = in[(size_t)wid * 64 + 32 + lane];
    float m = fmaxf(v0, v1);
#pragma unroll
    for (int o = 16; o > 0; o >>= 1) m = fmaxf(m, __shfl_xor_sync(0xffffffffu, m, o));
    float s = expf(v0 - m) + expf(v1 - m);
#pragma unroll
    for (int o = 16; o > 0; o >>= 1) s += __shfl_xor_sync(0xffffffffu, s, o);
    float l = m + logf(s);
    out[(size_t)wid * 64 + lane] = v0 - l;
    out[(size_t)wid * 64 + 32 + lane] = v1 - l;
}

// ---------------- launch ----------------
extern "C" void kernel_launch(void* const* d_in, const int* in_sizes, int n_in,
                              void* d_out, int out_size) {
    const float* x   = (const float*)d_in[0];
    const int*   src = (const int*)d_in[1];
    const int*   dst = (const int*)d_in[2];
    const float* W1l = (const float*)d_in[3];
    const float* W1r = (const float*)d_in[4];
    const float* b1  = (const float*)d_in[5];
    const float* g1  = (const float*)d_in[6];
    const float* be1 = (const float*)d_in[7];
    const float* rm1 = (const float*)d_in[8];
    const float* rv1 = (const float*)d_in[9];
    const float* W2l = (const float*)d_in[10];
    const float* W2r = (const float*)d_in[11];
    const float* b2  = (const float*)d_in[12];
    const float* g2  = (const float*)d_in[13];
    const float* be2 = (const float*)d_in[14];
    const float* rm2 = (const float*)d_in[15];
    const float* rv2 = (const float*)d_in[16];
    const float* W3l = (const float*)d_in[17];
    const float* W3r = (const float*)d_in[18];
    const float* b3  = (const float*)d_in[19];
    float* out = (float*)d_out;
    int E = in_sizes[1];

    float *p_agg, *p_h1, *p_h2, *p_t3, *p_agg3, *p_o3;
    cudaGetSymbolAddress((void**)&p_agg,  g_agg);
    cudaGetSymbolAddress((void**)&p_h1,   g_h1);
    cudaGetSymbolAddress((void**)&p_h2,   g_h2);
    cudaGetSymbolAddress((void**)&p_t3,   g_t3);
    cudaGetSymbolAddress((void**)&p_agg3, g_agg3);
    cudaGetSymbolAddress((void**)&p_o3,   g_o3);

    // CSR build (src/dst shared across all 3 layers)
    k_zero_deg<<<(NN + 255) / 256, 256>>>();
    k_hist<<<(E + 255) / 256, 256>>>(dst, E);
    k_scan1<<<NBLK_SCAN, 1024>>>();
    k_scan2<<<1, 32>>>();
    k_scan3<<<(NN + 1 + 255) / 256, 256>>>(E);
    k_scatter<<<(E + 255) / 256, 256>>>(src, dst, E);

    const int gemm_blocks = (NN + 127) / 128;

    // layer 1
    k_aggr128<<<NN / 8, 256>>>(x, p_agg);
    k_gemm_dual_bnrelu<<<gemm_blocks, 256>>>(p_agg, W1l, x, W1r,
                                             b1, g1, be1, rm1, rv1, p_h1);
    // layer 2
    k_aggr128<<<NN / 8, 256>>>(p_h1, p_agg);
    k_gemm_dual_bnrelu<<<gemm_blocks, 256>>>(p_agg, W2l, p_h1, W2r,
                                             b2, g2, be2, rm2, rv2, p_h2);
    // layer 3: transform-then-aggregate (agg is linear) to halve gather width
    k_gemm64<<<gemm_blocks, 256>>>(p_h2, W3l, nullptr, nullptr, p_t3);
    k_aggr64<<<NN / 8, 256>>>(p_t3, p_agg3);
    k_gemm64<<<gemm_blocks, 256>>>(p_h2, W3r, p_agg3, b3, p_o3);
    k_lsm<<<NN / 8, 256>>>(p_o3, out);
}

// round 3
// speedup vs baseline: 1.4954x; 1.2837x over previous
#include <cuda_runtime.h>
#include <cuda_bf16.h>
#include <math.h>
#include <stdint.h>

#define NN 100000
#define EE 1600000
#define NBLK_SCAN ((NN + 1023) / 1024)

// ---------------- device scratch (no allocations allowed) ----------------
__device__ int g_deg[NN];
__device__ int g_rowptr[NN + 1];
__device__ int g_fill[NN];
__device__ int g_csr[EE];
__device__ int g_blksum[NBLK_SCAN];

__device__ float g_agg[(size_t)NN * 128];
__device__ float g_h1[(size_t)NN * 128];
__device__ float g_h2[(size_t)NN * 128];
__device__ float g_t3[(size_t)NN * 64];
__device__ float g_agg3[(size_t)NN * 64];
__device__ float g_r3[(size_t)NN * 64];

// ---------------- CSR construction ----------------
__global__ void k_zero_deg() {
    int i = blockIdx.x * blockDim.x + threadIdx.x;
    if (i < NN) g_deg[i] = 0;
}

__global__ void k_hist(const int* __restrict__ dst, int E) {
    int e = blockIdx.x * blockDim.x + threadIdx.x;
    if (e < E) atomicAdd(&g_deg[dst[e]], 1);
}

__global__ void k_scan1() {
    __shared__ int s[1024];
    int i = threadIdx.x;
    int gid = blockIdx.x * 1024 + i;
    int v = (gid < NN) ? g_deg[gid] : 0;
    s[i] = v;
    __syncthreads();
    for (int off = 1; off < 1024; off <<= 1) {
        int add = (i >= off) ? s[i - off] : 0;
        __syncthreads();
        s[i] += add;
        __syncthreads();
    }
    if (gid < NN) g_rowptr[gid] = s[i] - v;
    if (i == 1023) g_blksum[blockIdx.x] = s[1023];
}

__global__ void k_scan2() {   // parallel exclusive scan over block sums (<=128)
    __shared__ int s[128];
    int i = threadIdx.x;
    int v = (i < NBLK_SCAN) ? g_blksum[i] : 0;
    s[i] = v;
    __syncthreads();
    for (int off = 1; off < 128; off <<= 1) {
        int a = (i >= off) ? s[i - off] : 0;
        __syncthreads();
        s[i] += a;
        __syncthreads();
    }
    if (i < NBLK_SCAN) g_blksum[i] = s[i] - v;
}

__global__ void k_scan3(int E) {
    int gid = blockIdx.x * blockDim.x + threadIdx.x;
    if (gid < NN) {
        int rp = g_rowptr[gid] + g_blksum[gid >> 10];
        g_rowptr[gid] = rp;
        g_fill[gid] = rp;
    } else if (gid == NN) {
        g_rowptr[NN] = E;
    }
}

__global__ void k_scatter(const int* __restrict__ src, const int* __restrict__ dst, int E) {
    int e = blockIdx.x * blockDim.x + threadIdx.x;
    if (e < E) {
        int p = atomicAdd(&g_fill[dst[e]], 1);
        g_csr[p] = src[e];
    }
}

// ---------------- mean aggregation (warp per node) ----------------
__global__ void k_aggr128(const float* __restrict__ xin, float* __restrict__ out) {
    int wid = blockIdx.x * (blockDim.x >> 5) + (threadIdx.x >> 5);
    int lane = threadIdx.x & 31;
    if (wid >= NN) return;
    int beg = g_rowptr[wid], end = g_rowptr[wid + 1];
    float4 acc = make_float4(0.f, 0.f, 0.f, 0.f);
    int j = beg;
    for (; j + 1 < end; j += 2) {
        int s0 = g_csr[j], s1 = g_csr[j + 1];
        float4 v0 = *(const float4*)(xin + (size_t)s0 * 128 + lane * 4);
        float4 v1 = *(const float4*)(xin + (size_t)s1 * 128 + lane * 4);
        acc.x += v0.x + v1.x; acc.y += v0.y + v1.y;
        acc.z += v0.z + v1.z; acc.w += v0.w + v1.w;
    }
    if (j < end) {
        int s0 = g_csr[j];
        float4 v0 = *(const float4*)(xin + (size_t)s0 * 128 + lane * 4);
        acc.x += v0.x; acc.y += v0.y; acc.z += v0.z; acc.w += v0.w;
    }
    float inv = 1.f / fmaxf((float)(end - beg), 1.f);
    acc.x *= inv; acc.y *= inv; acc.z *= inv; acc.w *= inv;
    *(float4*)(out + (size_t)wid * 128 + lane * 4) = acc;
}

__global__ void k_aggr64(const float* __restrict__ xin, float* __restrict__ out) {
    int wid = blockIdx.x * (blockDim.x >> 5) + (threadIdx.x >> 5);
    int lane = threadIdx.x & 31;
    if (wid >= NN) return;
    int beg = g_rowptr[wid], end = g_rowptr[wid + 1];
    float2 acc = make_float2(0.f, 0.f);
    int j = beg;
    for (; j + 1 < end; j += 2) {
        int s0 = g_csr[j], s1 = g_csr[j + 1];
        float2 v0 = *(const float2*)(xin + (size_t)s0 * 64 + lane * 2);
        float2 v1 = *(const float2*)(xin + (size_t)s1 * 64 + lane * 2);
        acc.x += v0.x + v1.x; acc.y += v0.y + v1.y;
    }
    if (j < end) {
        int s0 = g_csr[j];
        float2 v0 = *(const float2*)(xin + (size_t)s0 * 64 + lane * 2);
        acc.x += v0.x; acc.y += v0.y;
    }
    float inv = 1.f / fmaxf((float)(end - beg), 1.f);
    acc.x *= inv; acc.y *= inv;
    *(float2*)(out + (size_t)wid * 64 + lane * 2) = acc;
}

// ---------------- bf16 split helpers ----------------
// x = hi + lo, hi/lo bf16 (16 effective mantissa bits); D = hi*hi + hi*lo + lo*hi
__device__ __forceinline__ void bfsplit2(float v0, float v1, unsigned& hi, unsigned& lo) {
    __nv_bfloat16 h0 = __float2bfloat16(v0);
    __nv_bfloat16 h1 = __float2bfloat16(v1);
    float r0 = v0 - __bfloat162float(h0);
    float r1 = v1 - __bfloat162float(h1);
    __nv_bfloat16 l0 = __float2bfloat16(r0);
    __nv_bfloat16 l1 = __float2bfloat16(r1);
    hi = ((unsigned)__bfloat16_as_ushort(h1) << 16) | (unsigned)__bfloat16_as_ushort(h0);
    lo = ((unsigned)__bfloat16_as_ushort(l1) << 16) | (unsigned)__bfloat16_as_ushort(l0);
}

#define MMA_BF16(C, A, b0, b1)                                                \
    asm volatile(                                                             \
        "mma.sync.aligned.m16n8k16.row.col.f32.bf16.bf16.f32 "                \
        "{%0,%1,%2,%3},{%4,%5,%6,%7},{%8,%9},{%0,%1,%2,%3};"                  \
        : "+f"((C)[0]), "+f"((C)[1]), "+f"((C)[2]), "+f"((C)[3])              \
        : "r"((A)[0]), "r"((A)[1]), "r"((A)[2]), "r"((A)[3]),                 \
          "r"(b0), "r"(b1))

// smem word stride 12: fragment read pattern {12*g + tg} g=0..7,tg=0..3 hits
// 32 distinct banks (0-3,12-15,24-27,4-7,16-19,28-31,8-11,20-23)
#define SW 12

// ---------------- fused dual GEMM + BN + ReLU via bf16x2-split MMA ----------------
// out = relu( bn( A1@W1^T + A2@W2^T + bias ) )   [NN,128] x [128,128]
__global__ __launch_bounds__(256, 2) void k_gemm_dual_bnrelu(
    const float* __restrict__ A1, const float* __restrict__ W1,
    const float* __restrict__ A2, const float* __restrict__ W2,
    const float* __restrict__ bias, const float* __restrict__ gamma,
    const float* __restrict__ beta, const float* __restrict__ rmean,
    const float* __restrict__ rvar, float* __restrict__ out)
{
    __shared__ unsigned sAhi[128][SW], sAlo[128][SW];
    __shared__ unsigned sWhi[128][SW], sWlo[128][SW];
    __shared__ float s_sc[128], s_sh[128];

    const int t = threadIdx.x;
    const int lane = t & 31, wid = t >> 5;
    const int wr = wid & 3;       // warp row 0..3 (32 rows each)
    const int wc = wid >> 2;      // warp col 0..1 (64 cols each)
    const int g = lane >> 2, tg = lane & 3;
    const int row0 = blockIdx.x * 128;
    const int ar = t >> 1, ah = t & 1;   // fill: row, half-row

    if (t < 128) {
        float s = gamma[t] * rsqrtf(rvar[t] + 1e-5f);
        s_sc[t] = s;
        s_sh[t] = beta[t] + (bias[t] - rmean[t]) * s;
    }

    float c[2][8][4];
#pragma unroll
    for (int mt = 0; mt < 2; mt++)
#pragma unroll
        for (int nt = 0; nt < 8; nt++)
#pragma unroll
            for (int q = 0; q < 4; q++) c[mt][nt][q] = 0.f;

#pragma unroll
    for (int pass = 0; pass < 2; pass++) {
        const float* A = pass ? A2 : A1;
        const float* W = pass ? W2 : W1;
        for (int k0 = 0; k0 < 128; k0 += 16) {
            __syncthreads();
            // A chunk: 128 rows x 16 k; thread handles 8 floats (half row)
            {
                int gr = row0 + ar;
                float4 v0 = make_float4(0.f, 0.f, 0.f, 0.f), v1 = v0;
                if (gr < NN) {
                    const float* p = A + (size_t)gr * 128 + k0 + ah * 8;
                    v0 = *(const float4*)p;
                    v1 = *(const float4*)(p + 4);
                }
                unsigned h0, l0, h1, l1, h2, l2, h3, l3;
                bfsplit2(v0.x, v0.y, h0, l0);
                bfsplit2(v0.z, v0.w, h1, l1);
                bfsplit2(v1.x, v1.y, h2, l2);
                bfsplit2(v1.z, v1.w, h3, l3);
                *(uint4*)&sAhi[ar][ah * 4] = make_uint4(h0, h1, h2, h3);
                *(uint4*)&sAlo[ar][ah * 4] = make_uint4(l0, l1, l2, l3);
            }
            // W chunk: 128 rows x 16 k
            {
                const float* p = W + (size_t)ar * 128 + k0 + ah * 8;
                float4 v0 = *(const float4*)p;
                float4 v1 = *(const float4*)(p + 4);
                unsigned h0, l0, h1, l1, h2, l2, h3, l3;
                bfsplit2(v0.x, v0.y, h0, l0);
                bfsplit2(v0.z, v0.w, h1, l1);
                bfsplit2(v1.x, v1.y, h2, l2);
                bfsplit2(v1.z, v1.w, h3, l3);
                *(uint4*)&sWhi[ar][ah * 4] = make_uint4(h0, h1, h2, h3);
                *(uint4*)&sWlo[ar][ah * 4] = make_uint4(l0, l1, l2, l3);
            }
            __syncthreads();

            unsigned ahi[2][4], alo[2][4];
#pragma unroll
            for (int mt = 0; mt < 2; mt++) {
                int r = wr * 32 + mt * 16 + g;
                ahi[mt][0] = sAhi[r][tg];     ahi[mt][1] = sAhi[r + 8][tg];
                ahi[mt][2] = sAhi[r][tg + 4]; ahi[mt][3] = sAhi[r + 8][tg + 4];
                alo[mt][0] = sAlo[r][tg];     alo[mt][1] = sAlo[r + 8][tg];
                alo[mt][2] = sAlo[r][tg + 4]; alo[mt][3] = sAlo[r + 8][tg + 4];
            }
#pragma unroll
            for (int nt = 0; nt < 8; nt++) {
                int n = wc * 64 + nt * 8 + g;
                unsigned bh0 = sWhi[n][tg], bh1 = sWhi[n][tg + 4];
                unsigned bl0 = sWlo[n][tg], bl1 = sWlo[n][tg + 4];
#pragma unroll
                for (int mt = 0; mt < 2; mt++) {
                    MMA_BF16(c[mt][nt], ahi[mt], bh0, bh1);
                    MMA_BF16(c[mt][nt], ahi[mt], bl0, bl1);
                    MMA_BF16(c[mt][nt], alo[mt], bh0, bh1);
                }
            }
        }
    }

    // epilogue: BN + ReLU
#pragma unroll
    for (int mt = 0; mt < 2; mt++) {
#pragma unroll
        for (int i = 0; i < 2; i++) {
            int r = row0 + wr * 32 + mt * 16 + g + i * 8;
            if (r >= NN) continue;
#pragma unroll
            for (int nt = 0; nt < 8; nt++) {
                int col = wc * 64 + nt * 8 + 2 * tg;
                float v0 = c[mt][nt][2 * i];
                float v1 = c[mt][nt][2 * i + 1];
                v0 = fmaxf(v0 * s_sc[col] + s_sh[col], 0.f);
                v1 = fmaxf(v1 * s_sc[col + 1] + s_sh[col + 1], 0.f);
                *(float2*)(out + (size_t)r * 128 + col) = make_float2(v0, v1);
            }
        }
    }
}

// ---------------- layer-3 combined GEMM: A@[W3l;W3r]^T ----------------
// cols 0..63 -> t3 (to be aggregated), cols 64..127 -> r3 = A@W3r^T + b3
__global__ __launch_bounds__(256, 2) void k_gemm3(
    const float* __restrict__ A, const float* __restrict__ Wl,
    const float* __restrict__ Wr, const float* __restrict__ bias,
    float* __restrict__ t3, float* __restrict__ r3)
{
    __shared__ unsigned sAhi[128][SW], sAlo[128][SW];
    __shared__ unsigned sWhi[128][SW], sWlo[128][SW];

    const int t = threadIdx.x;
    const int lane = t & 31, wid = t >> 5;
    const int wr = wid & 3;
    const int wc = wid >> 2;
    const int g = lane >> 2, tg = lane & 3;
    const int row0 = blockIdx.x * 128;
    const int ar = t >> 1, ah = t & 1;

    float c[2][8][4];
#pragma unroll
    for (int mt = 0; mt < 2; mt++)
#pragma unroll
        for (int nt = 0; nt < 8; nt++)
#pragma unroll
            for (int q = 0; q < 4; q++) c[mt][nt][q] = 0.f;

    for (int k0 = 0; k0 < 128; k0 += 16) {
        __syncthreads();
        {
            int gr = row0 + ar;
            float4 v0 = make_float4(0.f, 0.f, 0.f, 0.f), v1 = v0;
            if (gr < NN) {
                const float* p = A + (size_t)gr * 128 + k0 + ah * 8;
                v0 = *(const float4*)p;
                v1 = *(const float4*)(p + 4);
            }
            unsigned h0, l0, h1, l1, h2, l2, h3, l3;
            bfsplit2(v0.x, v0.y, h0, l0);
            bfsplit2(v0.z, v0.w, h1, l1);
            bfsplit2(v1.x, v1.y, h2, l2);
            bfsplit2(v1.z, v1.w, h3, l3);
            *(uint4*)&sAhi[ar][ah * 4] = make_uint4(h0, h1, h2, h3);
            *(uint4*)&sAlo[ar][ah * 4] = make_uint4(l0, l1, l2, l3);
        }
        {
            const float* Wsrc = (ar < 64) ? (Wl + (size_t)ar * 128)
                                          : (Wr + (size_t)(ar - 64) * 128);
            const float* p = Wsrc + k0 + ah * 8;
            float4 v0 = *(const float4*)p;
            float4 v1 = *(const float4*)(p + 4);
            unsigned h0, l0, h1, l1, h2, l2, h3, l3;
            bfsplit2(v0.x, v0.y, h0, l0);
            bfsplit2(v0.z, v0.w, h1, l1);
            bfsplit2(v1.x, v1.y, h2, l2);
            bfsplit2(v1.z, v1.w, h3, l3);
            *(uint4*)&sWhi[ar][ah * 4] = make_uint4(h0, h1, h2, h3);
            *(uint4*)&sWlo[ar][ah * 4] = make_uint4(l0, l1, l2, l3);
        }
        __syncthreads();

        unsigned ahi[2][4], alo[2][4];
#pragma unroll
        for (int mt = 0; mt < 2; mt++) {
            int r = wr * 32 + mt * 16 + g;
            ahi[mt][0] = sAhi[r][tg];     ahi[mt][1] = sAhi[r + 8][tg];
            ahi[mt][2] = sAhi[r][tg + 4]; ahi[mt][3] = sAhi[r + 8][tg + 4];
            alo[mt][0] = sAlo[r][tg];     alo[mt][1] = sAlo[r + 8][tg];
            alo[mt][2] = sAlo[r][tg + 4]; alo[mt][3] = sAlo[r + 8][tg + 4];
        }
#pragma unroll
        for (int nt = 0; nt < 8; nt++) {
            int n = wc * 64 + nt * 8 + g;
            unsigned bh0 = sWhi[n][tg], bh1 = sWhi[n][tg + 4];
            unsigned bl0 = sWlo[n][tg], bl1 = sWlo[n][tg + 4];
#pragma unroll
            for (int mt = 0; mt < 2; mt++) {
                MMA_BF16(c[mt][nt], ahi[mt], bh0, bh1);
                MMA_BF16(c[mt][nt], ahi[mt], bl0, bl1);
                MMA_BF16(c[mt][nt], alo[mt], bh0, bh1);
            }
        }
    }

#pragma unroll
    for (int mt = 0; mt < 2; mt++) {
#pragma unroll
        for (int i = 0; i < 2; i++) {
            int r = row0 + wr * 32 + mt * 16 + g + i * 8;
            if (r >= NN) continue;
#pragma unroll
            for (int nt = 0; nt < 8; nt++) {
                int col = wc * 64 + nt * 8 + 2 * tg;   // 0..127
                float v0 = c[mt][nt][2 * i];
                float v1 = c[mt][nt][2 * i + 1];
                if (col < 64) {
                    *(float2*)(t3 + (size_t)r * 64 + col) = make_float2(v0, v1);
                } else {
                    int cc = col - 64;
                    v0 += bias[cc]; v1 += bias[cc + 1];
                    *(float2*)(r3 + (size_t)r * 64 + cc) = make_float2(v0, v1);
                }
            }
        }
    }
}

// ---------------- final: add + log_softmax over 64 (warp per row) ----------------
__global__ void k_lsm_final(const float* __restrict__ r3, const float* __restrict__ agg3,
                            float* __restrict__ out) {
    int wid = blockIdx.x * (blockDim.x >> 5) + (threadIdx.x >> 5);
    int lane = threadIdx.x & 31;
    if (wid >= NN) return;
    float v0 = r3[(size_t)wid * 64 + lane] + agg3[(size_t)wid * 64 + lane];
    float v1 = r3[(size_t)wid * 64 + 32 + lane] + agg3[(size_t)wid * 64 + 32 + lane];
    float m = fmaxf(v0, v1);
#pragma unroll
    for (int o = 16; o > 0; o >>= 1) m = fmaxf(m, __shfl_xor_sync(0xffffffffu, m, o));
    float s = expf(v0 - m) + expf(v1 - m);
#pragma unroll
    for (int o = 16; o > 0; o >>= 1) s += __shfl_xor_sync(0xffffffffu, s, o);
    float l = m + logf(s);
    out[(size_t)wid * 64 + lane] = v0 - l;
    out[(size_t)wid * 64 + 32 + lane] = v1 - l;
}

// ---------------- launch ----------------
extern "C" void kernel_launch(void* const* d_in, const int* in_sizes, int n_in,
                              void* d_out, int out_size) {
    const float* x   = (const float*)d_in[0];
    const int*   src = (const int*)d_in[1];
    const int*   dst = (const int*)d_in[2];
    const float* W1l = (const float*)d_in[3];
    const float* W1r = (const float*)d_in[4];
    const float* b1  = (const float*)d_in[5];
    const float* g1  = (const float*)d_in[6];
    const float* be1 = (const float*)d_in[7];
    const float* rm1 = (const float*)d_in[8];
    const float* rv1 = (const float*)d_in[9];
    const float* W2l = (const float*)d_in[10];
    const float* W2r = (const float*)d_in[11];
    const float* b2  = (const float*)d_in[12];
    const float* g2  = (const float*)d_in[13];
    const float* be2 = (const float*)d_in[14];
    const float* rm2 = (const float*)d_in[15];
    const float* rv2 = (const float*)d_in[16];
    const float* W3l = (const float*)d_in[17];
    const float* W3r = (const float*)d_in[18];
    const float* b3  = (const float*)d_in[19];
    float* out = (float*)d_out;
    int E = in_sizes[1];

    float *p_agg, *p_h1, *p_h2, *p_t3, *p_agg3, *p_r3;
    cudaGetSymbolAddress((void**)&p_agg,  g_agg);
    cudaGetSymbolAddress((void**)&p_h1,   g_h1);
    cudaGetSymbolAddress((void**)&p_h2,   g_h2);
    cudaGetSymbolAddress((void**)&p_t3,   g_t3);
    cudaGetSymbolAddress((void**)&p_agg3, g_agg3);
    cudaGetSymbolAddress((void**)&p_r3,   g_r3);

    // CSR build (src/dst shared across all 3 layers)
    k_zero_deg<<<(NN + 255) / 256, 256>>>();
    k_hist<<<(E + 255) / 256, 256>>>(dst, E);
    k_scan1<<<NBLK_SCAN, 1024>>>();
    k_scan2<<<1, 128>>>();
    k_scan3<<<(NN + 1 + 255) / 256, 256>>>(E);
    k_scatter<<<(E + 255) / 256, 256>>>(src, dst, E);

    const int gemm_blocks = (NN + 127) / 128;

    // layer 1
    k_aggr128<<<NN / 8, 256>>>(x, p_agg);
    k_gemm_dual_bnrelu<<<gemm_blocks, 256>>>(p_agg, W1l, x, W1r,
                                             b1, g1, be1, rm1, rv1, p_h1);
    // layer 2
    k_aggr128<<<NN / 8, 256>>>(p_h1, p_agg);
    k_gemm_dual_bnrelu<<<gemm_blocks, 256>>>(p_agg, W2l, p_h1, W2r,
                                             b2, g2, be2, rm2, rv2, p_h2);
    // layer 3: combined GEMM for both W3l (pre-aggregation) and W3r (+b3)
    k_gemm3<<<gemm_blocks, 256>>>(p_h2, W3l, W3r, b3, p_t3, p_r3);
    k_aggr64<<<NN / 8, 256>>>(p_t3, p_agg3);
    k_lsm_final<<<NN / 8, 256>>>(p_r3, p_agg3, out);
}

// round 4
// speedup vs baseline: 1.5166x; 1.0142x over previous
#include <cuda_runtime.h>
#include <cuda_bf16.h>
#include <cuda_fp16.h>
#include <math.h>
#include <stdint.h>

#define NN 100000
#define EE 1600000
#define NBLK_SCAN ((NN + 1023) / 1024)

// ---------------- device scratch (no allocations allowed) ----------------
__device__ int g_deg[NN];
__device__ int g_rowptr[NN + 1];
__device__ int g_fill[NN];
__device__ int g_csr[EE];
__device__ int g_blksum[NBLK_SCAN];

__device__ __half g_xh[(size_t)NN * 128];    // fp16 shadow of x
__device__ float  g_agg[(size_t)NN * 128];
__device__ float  g_h1[(size_t)NN * 128];
__device__ __half g_h1h[(size_t)NN * 128];   // fp16 shadow of h1
__device__ float  g_h2[(size_t)NN * 128];
__device__ __half g_t3h[(size_t)NN * 64];    // fp16 t3 (only ever gathered)
__device__ float  g_agg3[(size_t)NN * 64];
__device__ float  g_r3[(size_t)NN * 64];

// ---------------- CSR construction ----------------
__global__ void k_hist(const int* __restrict__ dst, int E) {
    int e = blockIdx.x * blockDim.x + threadIdx.x;
    if (e < E) atomicAdd(&g_deg[dst[e]], 1);
}

__global__ void k_scan1() {
    __shared__ int s[1024];
    int i = threadIdx.x;
    int gid = blockIdx.x * 1024 + i;
    int v = (gid < NN) ? g_deg[gid] : 0;
    s[i] = v;
    __syncthreads();
    for (int off = 1; off < 1024; off <<= 1) {
        int add = (i >= off) ? s[i - off] : 0;
        __syncthreads();
        s[i] += add;
        __syncthreads();
    }
    if (gid < NN) g_rowptr[gid] = s[i] - v;
    if (i == 1023) g_blksum[blockIdx.x] = s[1023];
}

__global__ void k_scan2() {   // parallel exclusive scan over block sums (<=128)
    __shared__ int s[128];
    int i = threadIdx.x;
    int v = (i < NBLK_SCAN) ? g_blksum[i] : 0;
    s[i] = v;
    __syncthreads();
    for (int off = 1; off < 128; off <<= 1) {
        int a = (i >= off) ? s[i - off] : 0;
        __syncthreads();
        s[i] += a;
        __syncthreads();
    }
    if (i < NBLK_SCAN) g_blksum[i] = s[i] - v;
}

__global__ void k_scan3(int E) {
    int gid = blockIdx.x * blockDim.x + threadIdx.x;
    if (gid < NN) {
        int rp = g_rowptr[gid] + g_blksum[gid >> 10];
        g_rowptr[gid] = rp;
        g_fill[gid] = rp;
        g_deg[gid] = 0;          // pre-zero for the NEXT call (module-load state is also 0)
    } else if (gid == NN) {
        g_rowptr[NN] = E;
    }
}

__global__ void k_scatter(const int* __restrict__ src, const int* __restrict__ dst, int E) {
    int e = blockIdx.x * blockDim.x + threadIdx.x;
    if (e < E) {
        int p = atomicAdd(&g_fill[dst[e]], 1);
        g_csr[p] = src[e];
    }
}

// ---------------- x -> fp16 shadow ----------------
__global__ void k_x2h(const float* __restrict__ x, __half* __restrict__ xh) {
    int i = blockIdx.x * blockDim.x + threadIdx.x;   // one float4 each
    if (i < NN * 32) {
        float4 v = ((const float4*)x)[i];
        __half2* o = (__half2*)xh + 2 * i;
        o[0] = __float22half2_rn(make_float2(v.x, v.y));
        o[1] = __float22half2_rn(make_float2(v.z, v.w));
    }
}

// ---------------- mean aggregation over fp16 rows (warp per node) ----------------
__device__ __forceinline__ void acc_h4(uint2 u, float* acc) {
    float2 f0 = __half22float2(*(__half2*)&u.x);
    float2 f1 = __half22float2(*(__half2*)&u.y);
    acc[0] += f0.x; acc[1] += f0.y; acc[2] += f1.x; acc[3] += f1.y;
}

__global__ void k_aggr128h(const __half* __restrict__ xh, float* __restrict__ out) {
    int wid = blockIdx.x * (blockDim.x >> 5) + (threadIdx.x >> 5);
    int lane = threadIdx.x & 31;
    if (wid >= NN) return;
    int beg = g_rowptr[wid], end = g_rowptr[wid + 1];
    const uint2* base = (const uint2*)xh;   // 128 halfs = 32 uint2 per row
    float acc[4] = {0.f, 0.f, 0.f, 0.f};
    int j = beg;
    for (; j + 3 < end; j += 4) {
        int s0 = g_csr[j], s1 = g_csr[j + 1], s2 = g_csr[j + 2], s3 = g_csr[j + 3];
        uint2 u0 = base[(size_t)s0 * 32 + lane];
        uint2 u1 = base[(size_t)s1 * 32 + lane];
        uint2 u2 = base[(size_t)s2 * 32 + lane];
        uint2 u3 = base[(size_t)s3 * 32 + lane];
        acc_h4(u0, acc); acc_h4(u1, acc); acc_h4(u2, acc); acc_h4(u3, acc);
    }
    for (; j < end; j++) {
        uint2 u0 = base[(size_t)g_csr[j] * 32 + lane];
        acc_h4(u0, acc);
    }
    float inv = 1.f / fmaxf((float)(end - beg), 1.f);
    *(float4*)(out + (size_t)wid * 128 + lane * 4) =
        make_float4(acc[0] * inv, acc[1] * inv, acc[2] * inv, acc[3] * inv);
}

__global__ void k_aggr64h(const __half* __restrict__ xh, float* __restrict__ out) {
    int wid = blockIdx.x * (blockDim.x >> 5) + (threadIdx.x >> 5);
    int lane = threadIdx.x & 31;
    if (wid >= NN) return;
    int beg = g_rowptr[wid], end = g_rowptr[wid + 1];
    const unsigned* base = (const unsigned*)xh;   // 64 halfs = 32 uints per row
    float a0 = 0.f, a1 = 0.f;
    int j = beg;
    for (; j + 3 < end; j += 4) {
        int s0 = g_csr[j], s1 = g_csr[j + 1], s2 = g_csr[j + 2], s3 = g_csr[j + 3];
        unsigned u0 = base[(size_t)s0 * 32 + lane];
        unsigned u1 = base[(size_t)s1 * 32 + lane];
        unsigned u2 = base[(size_t)s2 * 32 + lane];
        unsigned u3 = base[(size_t)s3 * 32 + lane];
        float2 f0 = __half22float2(*(__half2*)&u0);
        float2 f1 = __half22float2(*(__half2*)&u1);
        float2 f2 = __half22float2(*(__half2*)&u2);
        float2 f3 = __half22float2(*(__half2*)&u3);
        a0 += (f0.x + f1.x) + (f2.x + f3.x);
        a1 += (f0.y + f1.y) + (f2.y + f3.y);
    }
    for (; j < end; j++) {
        unsigned u0 = base[(size_t)g_csr[j] * 32 + lane];
        float2 f0 = __half22float2(*(__half2*)&u0);
        a0 += f0.x; a1 += f0.y;
    }
    float inv = 1.f / fmaxf((float)(end - beg), 1.f);
    *(float2*)(out + (size_t)wid * 64 + lane * 2) = make_float2(a0 * inv, a1 * inv);
}

// ---------------- bf16 split helpers ----------------
__device__ __forceinline__ void bfsplit2(float v0, float v1, unsigned& hi, unsigned& lo) {
    __nv_bfloat16 h0 = __float2bfloat16(v0);
    __nv_bfloat16 h1 = __float2bfloat16(v1);
    float r0 = v0 - __bfloat162float(h0);
    float r1 = v1 - __bfloat162float(h1);
    __nv_bfloat16 l0 = __float2bfloat16(r0);
    __nv_bfloat16 l1 = __float2bfloat16(r1);
    hi = ((unsigned)__bfloat16_as_ushort(h1) << 16) | (unsigned)__bfloat16_as_ushort(h0);
    lo = ((unsigned)__bfloat16_as_ushort(l1) << 16) | (unsigned)__bfloat16_as_ushort(l0);
}

#define MMA_BF16(C, A, b0, b1)                                                \
    asm volatile(                                                             \
        "mma.sync.aligned.m16n8k16.row.col.f32.bf16.bf16.f32 "                \
        "{%0,%1,%2,%3},{%4,%5,%6,%7},{%8,%9},{%0,%1,%2,%3};"                  \
        : "+f"((C)[0]), "+f"((C)[1]), "+f"((C)[2]), "+f"((C)[3])              \
        : "r"((A)[0]), "r"((A)[1]), "r"((A)[2]), "r"((A)[3]),                 \
          "r"(b0), "r"(b1))

#define SW 12   // stride 12 words: fragment reads hit 32 distinct banks

// ---------------- fused dual GEMM + BN + ReLU (layers 1,2) ----------------
// out = relu( bn( A1@W1^T + A2@W2^T + bias ) ); also writes fp16 shadow out16
__global__ __launch_bounds__(256, 2) void k_gemm_dual_bnrelu(
    const float* __restrict__ A1, const float* __restrict__ W1,
    const float* __restrict__ A2, const float* __restrict__ W2,
    const float* __restrict__ bias, const float* __restrict__ gamma,
    const float* __restrict__ beta, const float* __restrict__ rmean,
    const float* __restrict__ rvar, float* __restrict__ out,
    __half* __restrict__ out16)
{
    __shared__ unsigned sAhi[128][SW], sAlo[128][SW];
    __shared__ unsigned sWhi[128][SW], sWlo[128][SW];
    __shared__ float s_sc[128], s_sh[128];

    const int t = threadIdx.x;
    const int lane = t & 31, wid = t >> 5;
    const int wr = wid & 3;
    const int wc = wid >> 2;
    const int g = lane >> 2, tg = lane & 3;
    const int row0 = blockIdx.x * 128;
    const int ar = t >> 1, ah = t & 1;

    if (t < 128) {
        float s = gamma[t] * rsqrtf(rvar[t] + 1e-5f);
        s_sc[t] = s;
        s_sh[t] = beta[t] + (bias[t] - rmean[t]) * s;
    }

    float c[2][8][4];
#pragma unroll
    for (int mt = 0; mt < 2; mt++)
#pragma unroll
        for (int nt = 0; nt < 8; nt++)
#pragma unroll
            for (int q = 0; q < 4; q++) c[mt][nt][q] = 0.f;

#pragma unroll
    for (int pass = 0; pass < 2; pass++) {
        const float* A = pass ? A2 : A1;
        const float* W = pass ? W2 : W1;
        for (int k0 = 0; k0 < 128; k0 += 16) {
            __syncthreads();
            {
                int gr = row0 + ar;
                float4 v0 = make_float4(0.f, 0.f, 0.f, 0.f), v1 = v0;
                if (gr < NN) {
                    const float* p = A + (size_t)gr * 128 + k0 + ah * 8;
                    v0 = *(const float4*)p;
                    v1 = *(const float4*)(p + 4);
                }
                unsigned h0, l0, h1, l1, h2, l2, h3, l3;
                bfsplit2(v0.x, v0.y, h0, l0);
                bfsplit2(v0.z, v0.w, h1, l1);
                bfsplit2(v1.x, v1.y, h2, l2);
                bfsplit2(v1.z, v1.w, h3, l3);
                *(uint4*)&sAhi[ar][ah * 4] = make_uint4(h0, h1, h2, h3);
                *(uint4*)&sAlo[ar][ah * 4] = make_uint4(l0, l1, l2, l3);
            }
            {
                const float* p = W + (size_t)ar * 128 + k0 + ah * 8;
                float4 v0 = *(const float4*)p;
                float4 v1 = *(const float4*)(p + 4);
                unsigned h0, l0, h1, l1, h2, l2, h3, l3;
                bfsplit2(v0.x, v0.y, h0, l0);
                bfsplit2(v0.z, v0.w, h1, l1);
                bfsplit2(v1.x, v1.y, h2, l2);
                bfsplit2(v1.z, v1.w, h3, l3);
                *(uint4*)&sWhi[ar][ah * 4] = make_uint4(h0, h1, h2, h3);
                *(uint4*)&sWlo[ar][ah * 4] = make_uint4(l0, l1, l2, l3);
            }
            __syncthreads();

            unsigned ahi[2][4], alo[2][4];
#pragma unroll
            for (int mt = 0; mt < 2; mt++) {
                int r = wr * 32 + mt * 16 + g;
                ahi[mt][0] = sAhi[r][tg];     ahi[mt][1] = sAhi[r + 8][tg];
                ahi[mt][2] = sAhi[r][tg + 4]; ahi[mt][3] = sAhi[r + 8][tg + 4];
                alo[mt][0] = sAlo[r][tg];     alo[mt][1] = sAlo[r + 8][tg];
                alo[mt][2] = sAlo[r][tg + 4]; alo[mt][3] = sAlo[r + 8][tg + 4];
            }
#pragma unroll
            for (int nt = 0; nt < 8; nt++) {
                int n = wc * 64 + nt * 8 + g;
                unsigned bh0 = sWhi[n][tg], bh1 = sWhi[n][tg + 4];
                unsigned bl0 = sWlo[n][tg], bl1 = sWlo[n][tg + 4];
#pragma unroll
                for (int mt = 0; mt < 2; mt++) {
                    MMA_BF16(c[mt][nt], ahi[mt], bh0, bh1);
                    MMA_BF16(c[mt][nt], ahi[mt], bl0, bl1);
                    MMA_BF16(c[mt][nt], alo[mt], bh0, bh1);
                }
            }
        }
    }

#pragma unroll
    for (int mt = 0; mt < 2; mt++) {
#pragma unroll
        for (int i = 0; i < 2; i++) {
            int r = row0 + wr * 32 + mt * 16 + g + i * 8;
            if (r >= NN) continue;
#pragma unroll
            for (int nt = 0; nt < 8; nt++) {
                int col = wc * 64 + nt * 8 + 2 * tg;
                float v0 = c[mt][nt][2 * i];
                float v1 = c[mt][nt][2 * i + 1];
                v0 = fmaxf(v0 * s_sc[col] + s_sh[col], 0.f);
                v1 = fmaxf(v1 * s_sc[col + 1] + s_sh[col + 1], 0.f);
                *(float2*)(out + (size_t)r * 128 + col) = make_float2(v0, v1);
                if (out16)
                    *(__half2*)(out16 + (size_t)r * 128 + col) =
                        __float22half2_rn(make_float2(v0, v1));
            }
        }
    }
}

// ---------------- layer-3 combined GEMM: A@[W3l;W3r]^T ----------------
// cols 0..63 -> t3 (fp16, to be aggregated), cols 64..127 -> r3 = A@W3r^T + b3
__global__ __launch_bounds__(256, 2) void k_gemm3(
    const float* __restrict__ A, const float* __restrict__ Wl,
    const float* __restrict__ Wr, const float* __restrict__ bias,
    __half* __restrict__ t3h, float* __restrict__ r3)
{
    __shared__ unsigned sAhi[128][SW], sAlo[128][SW];
    __shared__ unsigned sWhi[128][SW], sWlo[128][SW];

    const int t = threadIdx.x;
    const int lane = t & 31, wid = t >> 5;
    const int wr = wid & 3;
    const int wc = wid >> 2;
    const int g = lane >> 2, tg = lane & 3;
    const int row0 = blockIdx.x * 128;
    const int ar = t >> 1, ah = t & 1;

    float c[2][8][4];
#pragma unroll
    for (int mt = 0; mt < 2; mt++)
#pragma unroll
        for (int nt = 0; nt < 8; nt++)
#pragma unroll
            for (int q = 0; q < 4; q++) c[mt][nt][q] = 0.f;

    for (int k0 = 0; k0 < 128; k0 += 16) {
        __syncthreads();
        {
            int gr = row0 + ar;
            float4 v0 = make_float4(0.f, 0.f, 0.f, 0.f), v1 = v0;
            if (gr < NN) {
                const float* p = A + (size_t)gr * 128 + k0 + ah * 8;
                v0 = *(const float4*)p;
                v1 = *(const float4*)(p + 4);
            }
            unsigned h0, l0, h1, l1, h2, l2, h3, l3;
            bfsplit2(v0.x, v0.y, h0, l0);
            bfsplit2(v0.z, v0.w, h1, l1);
            bfsplit2(v1.x, v1.y, h2, l2);
            bfsplit2(v1.z, v1.w, h3, l3);
            *(uint4*)&sAhi[ar][ah * 4] = make_uint4(h0, h1, h2, h3);
            *(uint4*)&sAlo[ar][ah * 4] = make_uint4(l0, l1, l2, l3);
        }
        {
            const float* Wsrc = (ar < 64) ? (Wl + (size_t)ar * 128)
                                          : (Wr + (size_t)(ar - 64) * 128);
            const float* p = Wsrc + k0 + ah * 8;
            float4 v0 = *(const float4*)p;
            float4 v1 = *(const float4*)(p + 4);
            unsigned h0, l0, h1, l1, h2, l2, h3, l3;
            bfsplit2(v0.x, v0.y, h0, l0);
            bfsplit2(v0.z, v0.w, h1, l1);
            bfsplit2(v1.x, v1.y, h2, l2);
            bfsplit2(v1.z, v1.w, h3, l3);
            *(uint4*)&sWhi[ar][ah * 4] = make_uint4(h0, h1, h2, h3);
            *(uint4*)&sWlo[ar][ah * 4] = make_uint4(l0, l1, l2, l3);
        }
        __syncthreads();

        unsigned ahi[2][4], alo[2][4];
#pragma unroll
        for (int mt = 0; mt < 2; mt++) {
            int r = wr * 32 + mt * 16 + g;
            ahi[mt][0] = sAhi[r][tg];     ahi[mt][1] = sAhi[r + 8][tg];
            ahi[mt][2] = sAhi[r][tg + 4]; ahi[mt][3] = sAhi[r + 8][tg + 4];
            alo[mt][0] = sAlo[r][tg];     alo[mt][1] = sAlo[r + 8][tg];
            alo[mt][2] = sAlo[r][tg + 4]; alo[mt][3] = sAlo[r + 8][tg + 4];
        }
#pragma unroll
        for (int nt = 0; nt < 8; nt++) {
            int n = wc * 64 + nt * 8 + g;
            unsigned bh0 = sWhi[n][tg], bh1 = sWhi[n][tg + 4];
            unsigned bl0 = sWlo[n][tg], bl1 = sWlo[n][tg + 4];
#pragma unroll
            for (int mt = 0; mt < 2; mt++) {
                MMA_BF16(c[mt][nt], ahi[mt], bh0, bh1);
                MMA_BF16(c[mt][nt], ahi[mt], bl0, bl1);
                MMA_BF16(c[mt][nt], alo[mt], bh0, bh1);
            }
        }
    }

#pragma unroll
    for (int mt = 0; mt < 2; mt++) {
#pragma unroll
        for (int i = 0; i < 2; i++) {
            int r = row0 + wr * 32 + mt * 16 + g + i * 8;
            if (r >= NN) continue;
#pragma unroll
            for (int nt = 0; nt < 8; nt++) {
                int col = wc * 64 + nt * 8 + 2 * tg;   // 0..127
                float v0 = c[mt][nt][2 * i];
                float v1 = c[mt][nt][2 * i + 1];
                if (col < 64) {
                    *(__half2*)(t3h + (size_t)r * 64 + col) =
                        __float22half2_rn(make_float2(v0, v1));
                } else {
                    int cc = col - 64;
                    v0 += bias[cc]; v1 += bias[cc + 1];
                    *(float2*)(r3 + (size_t)r * 64 + cc) = make_float2(v0, v1);
                }
            }
        }
    }
}

// ---------------- final: add + log_softmax over 64 (warp per row) ----------------
__global__ void k_lsm_final(const float* __restrict__ r3, const float* __restrict__ agg3,
                            float* __restrict__ out) {
    int wid = blockIdx.x * (blockDim.x >> 5) + (threadIdx.x >> 5);
    int lane = threadIdx.x & 31;
    if (wid >= NN) return;
    float v0 = r3[(size_t)wid * 64 + lane] + agg3[(size_t)wid * 64 + lane];
    float v1 = r3[(size_t)wid * 64 + 32 + lane] + agg3[(size_t)wid * 64 + 32 + lane];
    float m = fmaxf(v0, v1);
#pragma unroll
    for (int o = 16; o > 0; o >>= 1) m = fmaxf(m, __shfl_xor_sync(0xffffffffu, m, o));
    float s = expf(v0 - m) + expf(v1 - m);
#pragma unroll
    for (int o = 16; o > 0; o >>= 1) s += __shfl_xor_sync(0xffffffffu, s, o);
    float l = m + logf(s);
    out[(size_t)wid * 64 + lane] = v0 - l;
    out[(size_t)wid * 64 + 32 + lane] = v1 - l;
}

// ---------------- launch ----------------
extern "C" void kernel_launch(void* const* d_in, const int* in_sizes, int n_in,
                              void* d_out, int out_size) {
    const float* x   = (const float*)d_in[0];
    const int*   src = (const int*)d_in[1];
    const int*   dst = (const int*)d_in[2];
    const float* W1l = (const float*)d_in[3];
    const float* W1r = (const float*)d_in[4];
    const float* b1  = (const float*)d_in[5];
    const float* g1  = (const float*)d_in[6];
    const float* be1 = (const float*)d_in[7];
    const float* rm1 = (const float*)d_in[8];
    const float* rv1 = (const float*)d_in[9];
    const float* W2l = (const float*)d_in[10];
    const float* W2r = (const float*)d_in[11];
    const float* b2  = (const float*)d_in[12];
    const float* g2  = (const float*)d_in[13];
    const float* be2 = (const float*)d_in[14];
    const float* rm2 = (const float*)d_in[15];
    const float* rv2 = (const float*)d_in[16];
    const float* W3l = (const float*)d_in[17];
    const float* W3r = (const float*)d_in[18];
    const float* b3  = (const float*)d_in[19];
    float* out = (float*)d_out;
    int E = in_sizes[1];

    float *p_agg, *p_h1, *p_h2, *p_agg3, *p_r3;
    __half *p_xh, *p_h1h, *p_t3h;
    cudaGetSymbolAddress((void**)&p_agg,  g_agg);
    cudaGetSymbolAddress((void**)&p_h1,   g_h1);
    cudaGetSymbolAddress((void**)&p_h2,   g_h2);
    cudaGetSymbolAddress((void**)&p_agg3, g_agg3);
    cudaGetSymbolAddress((void**)&p_r3,   g_r3);
    cudaGetSymbolAddress((void**)&p_xh,   g_xh);
    cudaGetSymbolAddress((void**)&p_h1h,  g_h1h);
    cudaGetSymbolAddress((void**)&p_t3h,  g_t3h);

    // CSR build (g_deg is zeroed: initially by module load, then by k_scan3 each call)
    k_hist<<<(E + 255) / 256, 256>>>(dst, E);
    k_scan1<<<NBLK_SCAN, 1024>>>();
    k_scan2<<<1, 128>>>();
    k_scan3<<<(NN + 1 + 255) / 256, 256>>>(E);
    k_scatter<<<(E + 255) / 256, 256>>>(src, dst, E);

    // fp16 shadow of x
    k_x2h<<<(NN * 32 + 255) / 256, 256>>>(x, p_xh);

    const int gemm_blocks = (NN + 127) / 128;

    // layer 1
    k_aggr128h<<<NN / 8, 256>>>(p_xh, p_agg);
    k_gemm_dual_bnrelu<<<gemm_blocks, 256>>>(p_agg, W1l, x, W1r,
                                             b1, g1, be1, rm1, rv1, p_h1, p_h1h);
    // layer 2
    k_aggr128h<<<NN / 8, 256>>>(p_h1h, p_agg);
    k_gemm_dual_bnrelu<<<gemm_blocks, 256>>>(p_agg, W2l, p_h1, W2r,
                                             b2, g2, be2, rm2, rv2, p_h2, nullptr);
    // layer 3
    k_gemm3<<<gemm_blocks, 256>>>(p_h2, W3l, W3r, b3, p_t3h, p_r3);
    k_aggr64h<<<NN / 8, 256>>>(p_t3h, p_agg3);
    k_lsm_final<<<NN / 8, 256>>>(p_r3, p_agg3, out);
}